// round 1
// baseline (speedup 1.0000x reference)
#include <cuda_runtime.h>
#include <cuda_bf16.h>
#include <cstdint>

// Problem constants
#define BATCH   4
#define NSEQ    2048
#define DIM     1024
#define HEADS   16
#define HDIM    64          // DIM / HEADS
#define M_ROWS  (BATCH*NSEQ)     // 8192
#define N_COLS  (3*DIM)          // 3072
#define K_DIM   DIM              // 1024
#define SCALE   32.0f            // sqrt(DIM)

// Scratch (device globals — allocation-free per harness rules)
__device__ float g_Y[(size_t)M_ROWS * N_COLS];        // qkv projection output [8192, 3072]
__device__ float g_KVp[64 * 8 * HDIM * HDIM];         // per-(pair,split) partial k^T v
__device__ float g_KV[64 * HDIM * HDIM];              // reduced (k^T v) * scale per (b,h)

// ---------------------------------------------------------------------------
// Kernel A: Y = X @ W + bias   (M=8192, N=3072, K=1024), fp32 SGEMM
// 128x128 block tile, BK=16, 256 threads, 8x8 register tile per thread
// ---------------------------------------------------------------------------
#define BM 128
#define BN 128
#define BK 16
#define TM 8
#define TN 8

__global__ __launch_bounds__(256, 2)
void qkv_gemm(const float* __restrict__ A, const float* __restrict__ Bw,
              const float* __restrict__ bias)
{
    __shared__ float As[BK][BM];   // A stored transposed: As[k][m]
    __shared__ float Bs[BK][BN];

    const int tid     = threadIdx.x;
    const int rowBase = blockIdx.y * BM;
    const int colBase = blockIdx.x * BN;
    const int tr = tid / 16;       // 0..15
    const int tc = tid % 16;       // 0..15

    // A tile load mapping: 128 rows x 16 cols = 512 float4, 2 per thread
    const int aRow  = tid / 4;     // 0..63
    const int aCol4 = tid % 4;     // float4 column index (cols 4*aCol4 .. +3)
    // B tile load mapping: 16 rows x 128 cols = 512 float4, 2 per thread
    const int bRow  = tid / 32;    // 0..7
    const int bCol4 = tid % 32;

    float acc[TM][TN];
#pragma unroll
    for (int i = 0; i < TM; i++)
#pragma unroll
        for (int j = 0; j < TN; j++) acc[i][j] = 0.0f;

    for (int k0 = 0; k0 < K_DIM; k0 += BK) {
        // Load A tile (transposed into As)
#pragma unroll
        for (int r = 0; r < 2; r++) {
            int row = aRow + r * 64;
            float4 v = *(const float4*)(&A[(size_t)(rowBase + row) * K_DIM + k0 + aCol4 * 4]);
            As[aCol4 * 4 + 0][row] = v.x;
            As[aCol4 * 4 + 1][row] = v.y;
            As[aCol4 * 4 + 2][row] = v.z;
            As[aCol4 * 4 + 3][row] = v.w;
        }
        // Load B tile (direct copy, coalesced)
#pragma unroll
        for (int r = 0; r < 2; r++) {
            int row = bRow + r * 8;
            float4 v = *(const float4*)(&Bw[(size_t)(k0 + row) * N_COLS + colBase + bCol4 * 4]);
            *(float4*)(&Bs[row][bCol4 * 4]) = v;
        }
        __syncthreads();

#pragma unroll
        for (int kk = 0; kk < BK; kk++) {
            float ra[TM], rb[TN];
#pragma unroll
            for (int i = 0; i < TM; i += 4)
                *(float4*)&ra[i] = *(const float4*)&As[kk][tr * TM + i];
#pragma unroll
            for (int j = 0; j < TN; j += 4)
                *(float4*)&rb[j] = *(const float4*)&Bs[kk][tc * TN + j];
#pragma unroll
            for (int i = 0; i < TM; i++)
#pragma unroll
                for (int j = 0; j < TN; j++)
                    acc[i][j] += ra[i] * rb[j];
        }
        __syncthreads();
    }

    // Epilogue: add bias, store
#pragma unroll
    for (int i = 0; i < TM; i++) {
        int row = rowBase + tr * TM + i;
#pragma unroll
        for (int j = 0; j < TN; j += 4) {
            int col = colBase + tc * TN + j;
            float4 v;
            v.x = acc[i][j + 0] + bias[col + 0];
            v.y = acc[i][j + 1] + bias[col + 1];
            v.z = acc[i][j + 2] + bias[col + 2];
            v.w = acc[i][j + 3] + bias[col + 3];
            *(float4*)(&g_Y[(size_t)row * N_COLS + col]) = v;
        }
    }
}

// ---------------------------------------------------------------------------
// Kernel B: per (b,h) partial KV[d1][d2] = sum_n k[n][d1] * v[n][d2]
// grid = (64 pairs, 8 n-splits of 256), 256 threads; each thread owns 4x4 outs
// No atomics (deterministic) — partials reduced by kv_reduce.
// ---------------------------------------------------------------------------
__global__ __launch_bounds__(256)
void kv_partial()
{
    __shared__ float ks[32][HDIM];
    __shared__ float vs[32][HDIM];

    const int pair  = blockIdx.x;      // b*16 + h
    const int split = blockIdx.y;      // 0..7
    const int b = pair >> 4, h = pair & 15;
    const int tid = threadIdx.x;
    const int r4 = tid >> 4;           // 0..15 -> d1 group
    const int c4 = tid & 15;           // 0..15 -> d2 group

    float acc[4][4];
#pragma unroll
    for (int i = 0; i < 4; i++)
#pragma unroll
        for (int j = 0; j < 4; j++) acc[i][j] = 0.0f;

    const size_t rowBase = (size_t)b * NSEQ + (size_t)split * 256;
    const int colBase = h * HDIM * 3;   // + d*3 + {0:q,1:k,2:v}

    for (int s = 0; s < 8; s++) {
        const int n0 = s * 32;
        for (int e = tid; e < 32 * HDIM; e += 256) {
            int nn = e >> 6, d = e & 63;
            size_t base = (rowBase + n0 + nn) * N_COLS + colBase + d * 3;
            ks[nn][d] = g_Y[base + 1];
            vs[nn][d] = g_Y[base + 2];
        }
        __syncthreads();
#pragma unroll 4
        for (int nn = 0; nn < 32; nn++) {
            float ra[4], rb[4];
            *(float4*)ra = *(const float4*)&ks[nn][r4 * 4];
            *(float4*)rb = *(const float4*)&vs[nn][c4 * 4];
#pragma unroll
            for (int i = 0; i < 4; i++)
#pragma unroll
                for (int j = 0; j < 4; j++)
                    acc[i][j] += ra[i] * rb[j];
        }
        __syncthreads();
    }

    float* dst = g_KVp + ((size_t)pair * 8 + split) * (HDIM * HDIM);
#pragma unroll
    for (int i = 0; i < 4; i++)
#pragma unroll
        for (int j = 0; j < 4; j++)
            dst[(r4 * 4 + i) * HDIM + c4 * 4 + j] = acc[i][j];
}

// ---------------------------------------------------------------------------
// Kernel B2: reduce 8 split partials, fold in scale
// ---------------------------------------------------------------------------
__global__ __launch_bounds__(256)
void kv_reduce()
{
    int idx = blockIdx.x * 256 + threadIdx.x;        // 0 .. 64*4096-1
    int pair = idx >> 12, off = idx & 4095;
    const float* src = g_KVp + ((size_t)pair * 8) * 4096 + off;
    float s = 0.0f;
#pragma unroll
    for (int k = 0; k < 8; k++) s += src[(size_t)k * 4096];
    g_KV[idx] = s * SCALE;
}

// ---------------------------------------------------------------------------
// Kernel C: out[b,h,n,d] = q[b,n,h,:] @ (scale * KV[b,h])
// grid = (64 pairs, 16 n-chunks of 128), 256 threads
// ---------------------------------------------------------------------------
__global__ __launch_bounds__(256)
void out_gemm(float* __restrict__ out)
{
    __shared__ float qs[128][HDIM];     // 32 KB
    __shared__ float kvs[HDIM][HDIM];   // 16 KB

    const int pair = blockIdx.x;
    const int nc   = blockIdx.y;
    const int b = pair >> 4, h = pair & 15;
    const int tid = threadIdx.x;

    const size_t rowBase = (size_t)b * NSEQ + (size_t)nc * 128;
    const int colBase = h * HDIM * 3;

    for (int e = tid; e < 128 * HDIM; e += 256) {
        int r = e >> 6, d = e & 63;
        qs[r][d] = g_Y[(rowBase + r) * N_COLS + colBase + d * 3];   // kidx = 0 -> q
    }
    const float* kvsrc = g_KV + (size_t)pair * (HDIM * HDIM);
    for (int e = tid; e < HDIM * HDIM; e += 256)
        ((float*)kvs)[e] = kvsrc[e];
    __syncthreads();

    const int d4 = (tid & 15) * 4;     // 4 consecutive output dims
    const int rg = tid >> 4;           // row group 0..15
    float* obase = out + ((size_t)pair * NSEQ + (size_t)nc * 128) * HDIM;

#pragma unroll
    for (int ri = 0; ri < 8; ri++) {
        int r = rg + ri * 16;
        float a0 = 0.f, a1 = 0.f, a2 = 0.f, a3 = 0.f;
#pragma unroll 8
        for (int j = 0; j < HDIM; j++) {
            float q = qs[r][j];
            float4 kv = *(const float4*)&kvs[j][d4];
            a0 += q * kv.x; a1 += q * kv.y; a2 += q * kv.z; a3 += q * kv.w;
        }
        float4 o; o.x = a0; o.y = a1; o.z = a2; o.w = a3;
        *(float4*)&obase[(size_t)r * HDIM + d4] = o;
    }
}

// ---------------------------------------------------------------------------
// Launch
// ---------------------------------------------------------------------------
extern "C" void kernel_launch(void* const* d_in, const int* in_sizes, int n_in,
                              void* d_out, int out_size)
{
    (void)in_sizes; (void)n_in; (void)out_size;
    const float* x    = (const float*)d_in[0];   // [4, 2048, 1024]
    const float* W    = (const float*)d_in[1];   // [1024, 3072]
    const float* bias = (const float*)d_in[2];   // [3072]
    float* out = (float*)d_out;                  // [4, 16, 2048, 64]

    dim3 gA(N_COLS / BN, M_ROWS / BM);           // (24, 64)
    qkv_gemm<<<gA, 256>>>(x, W, bias);

    dim3 gB(64, 8);
    kv_partial<<<gB, 256>>>();

    kv_reduce<<<(64 * HDIM * HDIM) / 256, 256>>>();

    dim3 gC(64, 16);
    out_gemm<<<gC, 256>>>(out);
}

// round 3
// speedup vs baseline: 2.3590x; 2.3590x over previous
#include <cuda_runtime.h>
#include <cuda_bf16.h>
#include <cstdint>

// ---------------------------------------------------------------------------
// Problem constants
// ---------------------------------------------------------------------------
#define BATCH   4
#define NSEQ    2048
#define DIM     1024
#define HEADS   16
#define HDIM    64
#define M_ROWS  8192
#define N_COLS  3072
#define K_DIM   1024
#define SCALE   32.0f

// GEMM tiling (HMMA mma.sync path)
#define QBM 128
#define QBN 128
#define KCH 64                      // K elems per chunk (64 bf16 = 128B rows)
#define NCHUNK (K_DIM / KCH)        // 16
#define STAGE_BYTES 65536           // A_hi/A_lo/B_hi/B_lo, 16KB each
#define NSTAGE 3
#define SMEM_DYN (NSTAGE * STAGE_BYTES)   // 196608

// ---------------------------------------------------------------------------
// Scratch (device globals — allocation-free per harness rules)
// ---------------------------------------------------------------------------
__device__ __align__(16) __nv_bfloat16 g_Ahi[(size_t)M_ROWS * K_DIM];
__device__ __align__(16) __nv_bfloat16 g_Alo[(size_t)M_ROWS * K_DIM];
__device__ __align__(16) __nv_bfloat16 g_Bhi[(size_t)N_COLS * K_DIM];   // W^T
__device__ __align__(16) __nv_bfloat16 g_Blo[(size_t)N_COLS * K_DIM];
__device__ float g_Y[(size_t)M_ROWS * N_COLS];
__device__ float g_KVp[64 * 8 * HDIM * HDIM];
__device__ float g_KV[64 * HDIM * HDIM];

// ---------------------------------------------------------------------------
// Inline PTX (all valid on base sm_103 target: cp.async, ldmatrix, mma.sync)
// ---------------------------------------------------------------------------
__device__ __forceinline__ uint32_t smem_u32(const void* p) {
    uint32_t a;
    asm("{ .reg .u64 t; cvta.to.shared.u64 t, %1; cvt.u32.u64 %0, t; }" : "=r"(a) : "l"(p));
    return a;
}
__device__ __forceinline__ void cp16(uint32_t dst, const void* src) {
    asm volatile("cp.async.cg.shared.global [%0], [%1], 16;" :: "r"(dst), "l"(src));
}
__device__ __forceinline__ void ldsm4(uint32_t* r, uint32_t addr) {
    asm volatile("ldmatrix.sync.aligned.m8n8.x4.shared.b16 {%0,%1,%2,%3}, [%4];"
        : "=r"(r[0]), "=r"(r[1]), "=r"(r[2]), "=r"(r[3]) : "r"(addr));
}
__device__ __forceinline__ void ldsm2(uint32_t* r, uint32_t addr) {
    asm volatile("ldmatrix.sync.aligned.m8n8.x2.shared.b16 {%0,%1}, [%2];"
        : "=r"(r[0]), "=r"(r[1]) : "r"(addr));
}
__device__ __forceinline__ void hmma(float* d, const uint32_t* a, const uint32_t* b) {
    asm volatile("mma.sync.aligned.m16n8k16.row.col.f32.bf16.bf16.f32 "
        "{%0,%1,%2,%3}, {%4,%5,%6,%7}, {%8,%9}, {%0,%1,%2,%3};"
        : "+f"(d[0]), "+f"(d[1]), "+f"(d[2]), "+f"(d[3])
        : "r"(a[0]), "r"(a[1]), "r"(a[2]), "r"(a[3]), "r"(b[0]), "r"(b[1]));
}

// ---------------------------------------------------------------------------
// Conversion kernels: fp32 -> split bf16 (hi + lo)
// ---------------------------------------------------------------------------
__global__ __launch_bounds__(256)
void conv_x(const float4* __restrict__ x)
{
    size_t i = (size_t)blockIdx.x * 256 + threadIdx.x;
    float4 v = x[i];
    __nv_bfloat16 h[4], l[4];
    h[0] = __float2bfloat16(v.x); l[0] = __float2bfloat16(v.x - __bfloat162float(h[0]));
    h[1] = __float2bfloat16(v.y); l[1] = __float2bfloat16(v.y - __bfloat162float(h[1]));
    h[2] = __float2bfloat16(v.z); l[2] = __float2bfloat16(v.z - __bfloat162float(h[2]));
    h[3] = __float2bfloat16(v.w); l[3] = __float2bfloat16(v.w - __bfloat162float(h[3]));
    *(uint2*)(g_Ahi + 4 * i) = *(uint2*)h;
    *(uint2*)(g_Alo + 4 * i) = *(uint2*)l;
}

__global__ __launch_bounds__(256)
void conv_w(const float* __restrict__ W)
{
    __shared__ __nv_bfloat16 th[32][33], tl[32][33];
    const int n0 = blockIdx.x * 32;
    const int k0 = blockIdx.y * 32;
    const int cx = threadIdx.x & 31;
    const int ry = threadIdx.x >> 5;
#pragma unroll
    for (int r = ry; r < 32; r += 8) {
        float v = W[(size_t)(k0 + r) * N_COLS + n0 + cx];
        __nv_bfloat16 hh = __float2bfloat16(v);
        th[r][cx] = hh;
        tl[r][cx] = __float2bfloat16(v - __bfloat162float(hh));
    }
    __syncthreads();
#pragma unroll
    for (int r = ry; r < 32; r += 8) {
        g_Bhi[(size_t)(n0 + r) * K_DIM + k0 + cx] = th[cx][r];
        g_Blo[(size_t)(n0 + r) * K_DIM + k0 + cx] = tl[cx][r];
    }
}

// ---------------------------------------------------------------------------
// Kernel A: Y = X @ W + bias via mma.sync bf16, split-bf16 3-product
// grid (3072/128, 8192/128) = (24, 64), 256 threads (8 warps, 4x2)
// ---------------------------------------------------------------------------
__device__ __forceinline__ void load_chunk(uint32_t stage_sb, int rowBase, int colBase,
                                           int k0, int tid)
{
    // A: 2048 x 16B (hi+lo), B: 2048 x 16B (hi+lo); 16 per thread, coalesced
#pragma unroll
    for (int i = 0; i < 8; i++) {
        int o = tid + i * 256;
        int mat = o >> 10, idx = o & 1023, r = idx >> 3, ch = idx & 7;
        const __nv_bfloat16* src = (mat ? g_Alo : g_Ahi)
            + (size_t)(rowBase + r) * K_DIM + k0 + ch * 8;
        uint32_t dst = stage_sb + mat * 16384 + r * 128 + ((ch ^ (r & 7)) << 4);
        cp16(dst, src);
    }
#pragma unroll
    for (int i = 0; i < 8; i++) {
        int o = tid + i * 256;
        int mat = o >> 10, idx = o & 1023, r = idx >> 3, ch = idx & 7;
        const __nv_bfloat16* src = (mat ? g_Blo : g_Bhi)
            + (size_t)(colBase + r) * K_DIM + k0 + ch * 8;
        uint32_t dst = stage_sb + 32768 + mat * 16384 + r * 128 + ((ch ^ (r & 7)) << 4);
        cp16(dst, src);
    }
}

__global__ __launch_bounds__(256, 1)
void qkv_mma(const float* __restrict__ bias)
{
    extern __shared__ char smem[];
    const uint32_t sb = smem_u32(smem);
    const int tid = threadIdx.x;
    const int wid = tid >> 5, lid = tid & 31;
    const int warp_m = wid >> 1, warp_n = wid & 1;
    const int rowBase = blockIdx.y * QBM;
    const int colBase = blockIdx.x * QBN;

    float acc[2][8][4];
#pragma unroll
    for (int mt = 0; mt < 2; mt++)
#pragma unroll
        for (int nt = 0; nt < 8; nt++)
#pragma unroll
            for (int j = 0; j < 4; j++) acc[mt][nt][j] = 0.0f;

    // Prologue: fill 3 stages
#pragma unroll
    for (int c = 0; c < NSTAGE; c++) {
        load_chunk(sb + c * STAGE_BYTES, rowBase, colBase, c * KCH, tid);
        asm volatile("cp.async.commit_group;" ::: "memory");
    }

    // ldmatrix per-thread invariants
    const uint32_t aRowOff = (uint32_t)(warp_m * 32 + (lid & 15)) * 128;
    const uint32_t bRowOff = (uint32_t)(warp_n * 64 + (lid & 7)) * 128;
    const int xorC   = lid & 7;
    const int chSelA = lid >> 4;         // 0/1
    const int chSelB = (lid >> 3) & 1;   // 0/1

    for (int c = 0; c < NCHUNK; c++) {
        asm volatile("cp.async.wait_group 2;" ::: "memory");
        __syncthreads();
        const uint32_t st = sb + (uint32_t)(c % NSTAGE) * STAGE_BYTES;

#pragma unroll
        for (int ks = 0; ks < 4; ks++) {
            const uint32_t chA = (uint32_t)((ks * 2 + chSelA) ^ xorC) << 4;
            const uint32_t chB = (uint32_t)((ks * 2 + chSelB) ^ xorC) << 4;
            uint32_t ah[2][4], al[2][4];
#pragma unroll
            for (int mt = 0; mt < 2; mt++) {
                uint32_t off = aRowOff + mt * (16 * 128) + chA;
                ldsm4(ah[mt], st + off);
                ldsm4(al[mt], st + 16384 + off);
            }
            uint32_t bh[8][2], bl[8][2];
#pragma unroll
            for (int nt = 0; nt < 8; nt++) {
                uint32_t off = 32768 + bRowOff + nt * 1024 + chB;
                ldsm2(bh[nt], st + off);
                ldsm2(bl[nt], st + 16384 + off);
            }
#pragma unroll
            for (int mt = 0; mt < 2; mt++)
#pragma unroll
                for (int nt = 0; nt < 8; nt++) {
                    hmma(acc[mt][nt], ah[mt], bh[nt]);
                    hmma(acc[mt][nt], ah[mt], bl[nt]);
                    hmma(acc[mt][nt], al[mt], bh[nt]);
                }
        }
        __syncthreads();
        if (c + NSTAGE < NCHUNK)
            load_chunk(st, rowBase, colBase, (c + NSTAGE) * KCH, tid);
        asm volatile("cp.async.commit_group;" ::: "memory");
    }

    // Epilogue: + bias -> g_Y
    const int er = rowBase + warp_m * 32 + (lid >> 2);
    const int ec = colBase + warp_n * 64 + (lid & 3) * 2;
    float2 bb[8];
#pragma unroll
    for (int nt = 0; nt < 8; nt++) bb[nt] = *(const float2*)&bias[ec + nt * 8];
#pragma unroll
    for (int mt = 0; mt < 2; mt++) {
        const int r0 = er + mt * 16;
#pragma unroll
        for (int nt = 0; nt < 8; nt++) {
            float2 v0, v1;
            v0.x = acc[mt][nt][0] + bb[nt].x; v0.y = acc[mt][nt][1] + bb[nt].y;
            v1.x = acc[mt][nt][2] + bb[nt].x; v1.y = acc[mt][nt][3] + bb[nt].y;
            *(float2*)&g_Y[(size_t)r0 * N_COLS + ec + nt * 8] = v0;
            *(float2*)&g_Y[(size_t)(r0 + 8) * N_COLS + ec + nt * 8] = v1;
        }
    }
}

// ---------------------------------------------------------------------------
// Kernel B: per (b,h) partial KV[d1][d2] = sum_n k[n][d1] * v[n][d2]
// ---------------------------------------------------------------------------
__global__ __launch_bounds__(256)
void kv_partial()
{
    __shared__ float ks[32][HDIM];
    __shared__ float vs[32][HDIM];

    const int pair  = blockIdx.x;
    const int split = blockIdx.y;
    const int b = pair >> 4, h = pair & 15;
    const int tid = threadIdx.x;
    const int r4 = tid >> 4;
    const int c4 = tid & 15;

    float acc[4][4];
#pragma unroll
    for (int i = 0; i < 4; i++)
#pragma unroll
        for (int j = 0; j < 4; j++) acc[i][j] = 0.0f;

    const size_t rowBase = (size_t)b * NSEQ + (size_t)split * 256;
    const int colBase = h * HDIM * 3;

    for (int s = 0; s < 8; s++) {
        const int n0 = s * 32;
        for (int e = tid; e < 32 * HDIM; e += 256) {
            int nn = e >> 6, d = e & 63;
            size_t base = (rowBase + n0 + nn) * N_COLS + colBase + d * 3;
            ks[nn][d] = g_Y[base + 1];
            vs[nn][d] = g_Y[base + 2];
        }
        __syncthreads();
#pragma unroll 4
        for (int nn = 0; nn < 32; nn++) {
            float ra[4], rb[4];
            *(float4*)ra = *(const float4*)&ks[nn][r4 * 4];
            *(float4*)rb = *(const float4*)&vs[nn][c4 * 4];
#pragma unroll
            for (int i = 0; i < 4; i++)
#pragma unroll
                for (int j = 0; j < 4; j++)
                    acc[i][j] += ra[i] * rb[j];
        }
        __syncthreads();
    }

    float* dst = g_KVp + ((size_t)pair * 8 + split) * (HDIM * HDIM);
#pragma unroll
    for (int i = 0; i < 4; i++)
#pragma unroll
        for (int j = 0; j < 4; j++)
            dst[(r4 * 4 + i) * HDIM + c4 * 4 + j] = acc[i][j];
}

__global__ __launch_bounds__(256)
void kv_reduce()
{
    int idx = blockIdx.x * 256 + threadIdx.x;
    int pair = idx >> 12, off = idx & 4095;
    const float* src = g_KVp + ((size_t)pair * 8) * 4096 + off;
    float s = 0.0f;
#pragma unroll
    for (int k = 0; k < 8; k++) s += src[(size_t)k * 4096];
    g_KV[idx] = s * SCALE;
}

// ---------------------------------------------------------------------------
// Kernel C: out[b,h,n,d] = q[b,n,h,:] @ (scale * KV[b,h])
// ---------------------------------------------------------------------------
__global__ __launch_bounds__(256)
void out_gemm(float* __restrict__ out)
{
    __shared__ float qs[128][HDIM];
    __shared__ float kvs[HDIM][HDIM];

    const int pair = blockIdx.x;
    const int nc   = blockIdx.y;
    const int b = pair >> 4, h = pair & 15;
    const int tid = threadIdx.x;

    const size_t rowBase = (size_t)b * NSEQ + (size_t)nc * 128;
    const int colBase = h * HDIM * 3;

    for (int e = tid; e < 128 * HDIM; e += 256) {
        int r = e >> 6, d = e & 63;
        qs[r][d] = g_Y[(rowBase + r) * N_COLS + colBase + d * 3];
    }
    const float* kvsrc = g_KV + (size_t)pair * (HDIM * HDIM);
    for (int e = tid; e < HDIM * HDIM; e += 256)
        ((float*)kvs)[e] = kvsrc[e];
    __syncthreads();

    const int d4 = (tid & 15) * 4;
    const int rg = tid >> 4;
    float* obase = out + ((size_t)pair * NSEQ + (size_t)nc * 128) * HDIM;

#pragma unroll
    for (int ri = 0; ri < 8; ri++) {
        int r = rg + ri * 16;
        float a0 = 0.f, a1 = 0.f, a2 = 0.f, a3 = 0.f;
#pragma unroll 8
        for (int j = 0; j < HDIM; j++) {
            float q = qs[r][j];
            float4 kv = *(const float4*)&kvs[j][d4];
            a0 += q * kv.x; a1 += q * kv.y; a2 += q * kv.z; a3 += q * kv.w;
        }
        float4 o; o.x = a0; o.y = a1; o.z = a2; o.w = a3;
        *(float4*)&obase[(size_t)r * HDIM + d4] = o;
    }
}

// ---------------------------------------------------------------------------
// Host launch
// ---------------------------------------------------------------------------
extern "C" void kernel_launch(void* const* d_in, const int* in_sizes, int n_in,
                              void* d_out, int out_size)
{
    (void)in_sizes; (void)n_in; (void)out_size;
    const float* x    = (const float*)d_in[0];
    const float* W    = (const float*)d_in[1];
    const float* bias = (const float*)d_in[2];
    float* out = (float*)d_out;

    conv_x<<<(M_ROWS * K_DIM / 4) / 256, 256>>>((const float4*)x);
    conv_w<<<dim3(N_COLS / 32, K_DIM / 32), 256>>>(W);

    static int smem_set = 0;
    if (!smem_set) {
        cudaFuncSetAttribute(qkv_mma, cudaFuncAttributeMaxDynamicSharedMemorySize, SMEM_DYN);
        smem_set = 1;
    }
    qkv_mma<<<dim3(N_COLS / QBN, M_ROWS / QBM), 256, SMEM_DYN>>>(bias);

    kv_partial<<<dim3(64, 8), 256>>>();
    kv_reduce<<<(64 * HDIM * HDIM) / 256, 256>>>();
    out_gemm<<<dim3(64, 16), 256>>>(out);
}

// round 4
// speedup vs baseline: 3.2141x; 1.3625x over previous
#include <cuda_runtime.h>
#include <cuda_bf16.h>
#include <cuda_fp16.h>
#include <cstdint>

// ---------------------------------------------------------------------------
// Problem constants
// ---------------------------------------------------------------------------
#define BATCH   4
#define NSEQ    2048
#define DIM     1024
#define HEADS   16
#define HDIM    64
#define M_ROWS  8192
#define N_COLS  3072
#define K_DIM   1024
#define SCALE   32.0f

// GEMM tiling (HMMA mma.sync path)
#define QBM 128
#define QBN 128
#define KCH 64                      // K elems per chunk (64 fp16 = 128B rows)
#define NCHUNK (K_DIM / KCH)        // 16
#define STAGE_BYTES 49152           // A(16KB) + B_hi(16KB) + B_lo(16KB)
#define NSTAGE 4
#define SMEM_DYN (NSTAGE * STAGE_BYTES)   // 196608

// ---------------------------------------------------------------------------
// Scratch (device globals — allocation-free per harness rules)
// ---------------------------------------------------------------------------
__device__ __align__(16) __half g_Ah[(size_t)M_ROWS * K_DIM];      // fp16(x)
__device__ __align__(16) __half g_Bh[(size_t)N_COLS * K_DIM];      // W^T permuted, hi
__device__ __align__(16) __half g_Bl[(size_t)N_COLS * K_DIM];      // W^T permuted, lo
__device__ float g_biasP[N_COLS];                                  // permuted bias
// Y layout (permuted): [row][t*1024 + h*64 + d]  (t: 0=q,1=k,2=v)
__device__ float g_Y[(size_t)M_ROWS * N_COLS];
__device__ float g_KVp[64 * 8 * HDIM * HDIM];
__device__ float g_KV[64 * HDIM * HDIM];

// ---------------------------------------------------------------------------
// Inline PTX (valid on base sm_103 target)
// ---------------------------------------------------------------------------
__device__ __forceinline__ uint32_t smem_u32(const void* p) {
    uint32_t a;
    asm("{ .reg .u64 t; cvta.to.shared.u64 t, %1; cvt.u32.u64 %0, t; }" : "=r"(a) : "l"(p));
    return a;
}
__device__ __forceinline__ void cp16(uint32_t dst, const void* src) {
    asm volatile("cp.async.cg.shared.global [%0], [%1], 16;" :: "r"(dst), "l"(src));
}
__device__ __forceinline__ void ldsm4(uint32_t* r, uint32_t addr) {
    asm volatile("ldmatrix.sync.aligned.m8n8.x4.shared.b16 {%0,%1,%2,%3}, [%4];"
        : "=r"(r[0]), "=r"(r[1]), "=r"(r[2]), "=r"(r[3]) : "r"(addr));
}
__device__ __forceinline__ void ldsm2(uint32_t* r, uint32_t addr) {
    asm volatile("ldmatrix.sync.aligned.m8n8.x2.shared.b16 {%0,%1}, [%2];"
        : "=r"(r[0]), "=r"(r[1]) : "r"(addr));
}
__device__ __forceinline__ void hmma(float* d, const uint32_t* a, const uint32_t* b) {
    asm volatile("mma.sync.aligned.m16n8k16.row.col.f32.f16.f16.f32 "
        "{%0,%1,%2,%3}, {%4,%5,%6,%7}, {%8,%9}, {%0,%1,%2,%3};"
        : "+f"(d[0]), "+f"(d[1]), "+f"(d[2]), "+f"(d[3])
        : "r"(a[0]), "r"(a[1]), "r"(a[2]), "r"(a[3]), "r"(b[0]), "r"(b[1]));
}

// ---------------------------------------------------------------------------
// conv_x: fp32 x -> fp16 (single)
// ---------------------------------------------------------------------------
__global__ __launch_bounds__(256)
void conv_x(const float4* __restrict__ x)
{
    size_t i = (size_t)blockIdx.x * 256 + threadIdx.x;
    float4 v = x[i];
    __half h[4];
    h[0] = __float2half(v.x); h[1] = __float2half(v.y);
    h[2] = __float2half(v.z); h[3] = __float2half(v.w);
    *(uint2*)(g_Ah + 4 * i) = *(uint2*)h;
}

// ---------------------------------------------------------------------------
// conv_w: W [k][c] -> permuted transposed split-fp16  g_B{h,l}[c'][k]
// c = h*192 + d*3 + t  ->  c' = t*1024 + h*64 + d
// grid (16 h, 32 k0-tiles), 256 threads
// ---------------------------------------------------------------------------
__global__ __launch_bounds__(256)
void conv_w(const float* __restrict__ W)
{
    __shared__ float tile[32][193];
    const int h  = blockIdx.x;
    const int k0 = blockIdx.y * 32;
    const int tid = threadIdx.x;

    for (int e = tid; e < 32 * 192; e += 256) {
        int r = e / 192, cc = e % 192;
        tile[r][cc] = W[(size_t)(k0 + r) * N_COLS + h * 192 + cc];
    }
    __syncthreads();

    for (int e = tid; e < 3 * 64 * 32; e += 256) {
        int t = e >> 11;
        int rem = e & 2047;
        int d = rem >> 5, kk = rem & 31;
        float v = tile[kk][d * 3 + t];
        __half hi = __float2half(v);
        __half lo = __float2half(v - __half2float(hi));
        size_t cp = (size_t)(t * 1024 + h * 64 + d) * K_DIM + k0 + kk;
        g_Bh[cp] = hi;
        g_Bl[cp] = lo;
    }
}

__global__ __launch_bounds__(256)
void bias_perm(const float* __restrict__ bias)
{
    int cp = blockIdx.x * 256 + threadIdx.x;     // c'
    int t = cp >> 10, hd = cp & 1023, h = hd >> 6, d = hd & 63;
    g_biasP[cp] = bias[h * 192 + d * 3 + t];
}

// ---------------------------------------------------------------------------
// Kernel A: Y = X @ W' + bias' via mma.sync fp16, 2-product (A single, B split)
// grid (24, 64), 256 threads (8 warps, 4x2)
// ---------------------------------------------------------------------------
__device__ __forceinline__ void load_chunk(uint32_t stage_sb, int rowBase, int colBase,
                                           int k0, int tid)
{
    // A: 1024 x 16B; B hi/lo: 2048 x 16B; 12 cp16 per thread, coalesced
#pragma unroll
    for (int i = 0; i < 4; i++) {
        int o = tid + i * 256;
        int r = o >> 3, ch = o & 7;
        const __half* src = g_Ah + (size_t)(rowBase + r) * K_DIM + k0 + ch * 8;
        uint32_t dst = stage_sb + r * 128 + ((ch ^ (r & 7)) << 4);
        cp16(dst, src);
    }
#pragma unroll
    for (int i = 0; i < 8; i++) {
        int o = tid + i * 256;
        int mat = o >> 10, idx = o & 1023, r = idx >> 3, ch = idx & 7;
        const __half* src = (mat ? g_Bl : g_Bh)
            + (size_t)(colBase + r) * K_DIM + k0 + ch * 8;
        uint32_t dst = stage_sb + 16384 + mat * 16384 + r * 128 + ((ch ^ (r & 7)) << 4);
        cp16(dst, src);
    }
}

__global__ __launch_bounds__(256, 1)
void qkv_mma()
{
    extern __shared__ char smem[];
    const uint32_t sb = smem_u32(smem);
    const int tid = threadIdx.x;
    const int wid = tid >> 5, lid = tid & 31;
    const int warp_m = wid >> 1, warp_n = wid & 1;
    const int rowBase = blockIdx.y * QBM;
    const int colBase = blockIdx.x * QBN;

    float acc[2][8][4];
#pragma unroll
    for (int mt = 0; mt < 2; mt++)
#pragma unroll
        for (int nt = 0; nt < 8; nt++)
#pragma unroll
            for (int j = 0; j < 4; j++) acc[mt][nt][j] = 0.0f;

    // Prologue: fill all 4 stages
#pragma unroll
    for (int c = 0; c < NSTAGE; c++) {
        load_chunk(sb + c * STAGE_BYTES, rowBase, colBase, c * KCH, tid);
        asm volatile("cp.async.commit_group;" ::: "memory");
    }

    const uint32_t aRowOff = (uint32_t)(warp_m * 32 + (lid & 15)) * 128;
    const uint32_t bRowOff = (uint32_t)(warp_n * 64 + (lid & 7)) * 128;
    const int xorC   = lid & 7;
    const int chSelA = lid >> 4;
    const int chSelB = (lid >> 3) & 1;

    for (int c = 0; c < NCHUNK; c++) {
        asm volatile("cp.async.wait_group 3;" ::: "memory");
        __syncthreads();
        const uint32_t st = sb + (uint32_t)(c % NSTAGE) * STAGE_BYTES;

#pragma unroll
        for (int ks = 0; ks < 4; ks++) {
            const uint32_t chA = (uint32_t)((ks * 2 + chSelA) ^ xorC) << 4;
            const uint32_t chB = (uint32_t)((ks * 2 + chSelB) ^ xorC) << 4;
            uint32_t ah[2][4];
#pragma unroll
            for (int mt = 0; mt < 2; mt++)
                ldsm4(ah[mt], st + aRowOff + mt * (16 * 128) + chA);
            uint32_t bh[8][2], bl[8][2];
#pragma unroll
            for (int nt = 0; nt < 8; nt++) {
                uint32_t off = 16384 + bRowOff + nt * 1024 + chB;
                ldsm2(bh[nt], st + off);
                ldsm2(bl[nt], st + 16384 + off);
            }
#pragma unroll
            for (int mt = 0; mt < 2; mt++)
#pragma unroll
                for (int nt = 0; nt < 8; nt++) {
                    hmma(acc[mt][nt], ah[mt], bh[nt]);
                    hmma(acc[mt][nt], ah[mt], bl[nt]);
                }
        }
        __syncthreads();
        if (c + NSTAGE < NCHUNK)
            load_chunk(st, rowBase, colBase, (c + NSTAGE) * KCH, tid);
        asm volatile("cp.async.commit_group;" ::: "memory");
    }

    // Epilogue: + permuted bias -> g_Y
    const int er = rowBase + warp_m * 32 + (lid >> 2);
    const int ec = colBase + warp_n * 64 + (lid & 3) * 2;
    float2 bb[8];
#pragma unroll
    for (int nt = 0; nt < 8; nt++) bb[nt] = *(const float2*)&g_biasP[ec + nt * 8];
#pragma unroll
    for (int mt = 0; mt < 2; mt++) {
        const int r0 = er + mt * 16;
#pragma unroll
        for (int nt = 0; nt < 8; nt++) {
            float2 v0, v1;
            v0.x = acc[mt][nt][0] + bb[nt].x; v0.y = acc[mt][nt][1] + bb[nt].y;
            v1.x = acc[mt][nt][2] + bb[nt].x; v1.y = acc[mt][nt][3] + bb[nt].y;
            *(float2*)&g_Y[(size_t)r0 * N_COLS + ec + nt * 8] = v0;
            *(float2*)&g_Y[(size_t)(r0 + 8) * N_COLS + ec + nt * 8] = v1;
        }
    }
}

// ---------------------------------------------------------------------------
// Kernel B: per (b,h) partial KV[d1][d2] = sum_n k[n][d1] * v[n][d2]
// Layout-permuted Y: K plane at col 1024 + h*64, V plane at 2048 + h*64
// ---------------------------------------------------------------------------
__global__ __launch_bounds__(256)
void kv_partial()
{
    __shared__ float ks[32][HDIM];
    __shared__ float vs[32][HDIM];

    const int pair  = blockIdx.x;
    const int split = blockIdx.y;
    const int b = pair >> 4, h = pair & 15;
    const int tid = threadIdx.x;
    const int r4 = tid >> 4;
    const int c4 = tid & 15;

    float acc[4][4];
#pragma unroll
    for (int i = 0; i < 4; i++)
#pragma unroll
        for (int j = 0; j < 4; j++) acc[i][j] = 0.0f;

    const size_t rowBase = (size_t)b * NSEQ + (size_t)split * 256;
    const int kCol = 1024 + h * HDIM;
    const int vCol = 2048 + h * HDIM;

    for (int s = 0; s < 8; s++) {
        const int n0 = s * 32;
        for (int e = tid; e < 32 * HDIM; e += 256) {
            int nn = e >> 6, d = e & 63;
            size_t base = (rowBase + n0 + nn) * N_COLS;
            ks[nn][d] = g_Y[base + kCol + d];
            vs[nn][d] = g_Y[base + vCol + d];
        }
        __syncthreads();
#pragma unroll 4
        for (int nn = 0; nn < 32; nn++) {
            float ra[4], rb[4];
            *(float4*)ra = *(const float4*)&ks[nn][r4 * 4];
            *(float4*)rb = *(const float4*)&vs[nn][c4 * 4];
#pragma unroll
            for (int i = 0; i < 4; i++)
#pragma unroll
                for (int j = 0; j < 4; j++)
                    acc[i][j] += ra[i] * rb[j];
        }
        __syncthreads();
    }

    float* dst = g_KVp + ((size_t)pair * 8 + split) * (HDIM * HDIM);
#pragma unroll
    for (int i = 0; i < 4; i++)
#pragma unroll
        for (int j = 0; j < 4; j++)
            dst[(r4 * 4 + i) * HDIM + c4 * 4 + j] = acc[i][j];
}

__global__ __launch_bounds__(256)
void kv_reduce()
{
    int idx = blockIdx.x * 256 + threadIdx.x;
    int pair = idx >> 12, off = idx & 4095;
    const float* src = g_KVp + ((size_t)pair * 8) * 4096 + off;
    float s = 0.0f;
#pragma unroll
    for (int k = 0; k < 8; k++) s += src[(size_t)k * 4096];
    g_KV[idx] = s * SCALE;
}

// ---------------------------------------------------------------------------
// Kernel C: out = q @ KV   (j-outer, 32 independent accumulators/thread)
// grid (64 pairs, 16 row-chunks of 128), 256 threads, dynamic smem
// ---------------------------------------------------------------------------
#define SMEM_OUT (128 * 65 * 4 + 64 * 64 * 4)   // 49664

__global__ __launch_bounds__(256)
void out_gemm(float* __restrict__ out)
{
    extern __shared__ char smc[];
    float (*qs)[65] = (float(*)[65])smc;
    float (*kvs)[64] = (float(*)[64])(smc + 128 * 65 * 4);

    const int pair = blockIdx.x;
    const int nc   = blockIdx.y;
    const int b = pair >> 4, h = pair & 15;
    const int tid = threadIdx.x;

    const size_t rowBase = (size_t)b * NSEQ + (size_t)nc * 128;
    const int qCol = h * HDIM;       // t=0 plane

    for (int e = tid; e < 128 * HDIM; e += 256) {
        int r = e >> 6, d = e & 63;
        qs[r][d] = g_Y[(rowBase + r) * N_COLS + qCol + d];
    }
    const float* kvsrc = g_KV + (size_t)pair * (HDIM * HDIM);
    for (int e = tid; e < HDIM * HDIM; e += 256)
        ((float*)kvs)[e] = kvsrc[e];
    __syncthreads();

    const int dg = (tid & 7) * 8;       // 8 output dims
    const int rg = (tid >> 3) * 4;      // 4 rows

    float acc[4][8];
#pragma unroll
    for (int i = 0; i < 4; i++)
#pragma unroll
        for (int j = 0; j < 8; j++) acc[i][j] = 0.0f;

#pragma unroll 4
    for (int j = 0; j < HDIM; j++) {
        float4 kv0 = *(const float4*)&kvs[j][dg];
        float4 kv1 = *(const float4*)&kvs[j][dg + 4];
        float q0 = qs[rg + 0][j], q1 = qs[rg + 1][j];
        float q2 = qs[rg + 2][j], q3 = qs[rg + 3][j];
        acc[0][0] += q0 * kv0.x; acc[0][1] += q0 * kv0.y; acc[0][2] += q0 * kv0.z; acc[0][3] += q0 * kv0.w;
        acc[0][4] += q0 * kv1.x; acc[0][5] += q0 * kv1.y; acc[0][6] += q0 * kv1.z; acc[0][7] += q0 * kv1.w;
        acc[1][0] += q1 * kv0.x; acc[1][1] += q1 * kv0.y; acc[1][2] += q1 * kv0.z; acc[1][3] += q1 * kv0.w;
        acc[1][4] += q1 * kv1.x; acc[1][5] += q1 * kv1.y; acc[1][6] += q1 * kv1.z; acc[1][7] += q1 * kv1.w;
        acc[2][0] += q2 * kv0.x; acc[2][1] += q2 * kv0.y; acc[2][2] += q2 * kv0.z; acc[2][3] += q2 * kv0.w;
        acc[2][4] += q2 * kv1.x; acc[2][5] += q2 * kv1.y; acc[2][6] += q2 * kv1.z; acc[2][7] += q2 * kv1.w;
        acc[3][0] += q3 * kv0.x; acc[3][1] += q3 * kv0.y; acc[3][2] += q3 * kv0.z; acc[3][3] += q3 * kv0.w;
        acc[3][4] += q3 * kv1.x; acc[3][5] += q3 * kv1.y; acc[3][6] += q3 * kv1.z; acc[3][7] += q3 * kv1.w;
    }

    float* obase = out + ((size_t)pair * NSEQ + (size_t)nc * 128) * HDIM;
#pragma unroll
    for (int rr = 0; rr < 4; rr++) {
        *(float4*)&obase[(size_t)(rg + rr) * HDIM + dg]     = *(float4*)&acc[rr][0];
        *(float4*)&obase[(size_t)(rg + rr) * HDIM + dg + 4] = *(float4*)&acc[rr][4];
    }
}

// ---------------------------------------------------------------------------
// Host launch
// ---------------------------------------------------------------------------
extern "C" void kernel_launch(void* const* d_in, const int* in_sizes, int n_in,
                              void* d_out, int out_size)
{
    (void)in_sizes; (void)n_in; (void)out_size;
    const float* x    = (const float*)d_in[0];
    const float* W    = (const float*)d_in[1];
    const float* bias = (const float*)d_in[2];
    float* out = (float*)d_out;

    static int attr_set = 0;
    if (!attr_set) {
        cudaFuncSetAttribute(qkv_mma, cudaFuncAttributeMaxDynamicSharedMemorySize, SMEM_DYN);
        cudaFuncSetAttribute(out_gemm, cudaFuncAttributeMaxDynamicSharedMemorySize, SMEM_OUT);
        attr_set = 1;
    }

    conv_x<<<(M_ROWS * K_DIM / 4) / 256, 256>>>((const float4*)x);
    conv_w<<<dim3(16, 32), 256>>>(W);
    bias_perm<<<N_COLS / 256, 256>>>(bias);

    qkv_mma<<<dim3(N_COLS / QBN, M_ROWS / QBM), 256, SMEM_DYN>>>();

    kv_partial<<<dim3(64, 8), 256>>>();
    kv_reduce<<<(64 * HDIM * HDIM) / 256, 256>>>();
    out_gemm<<<dim3(64, 16), 256, SMEM_OUT>>>(out);
}

// round 5
// speedup vs baseline: 4.8281x; 1.5022x over previous
#include <cuda_runtime.h>
#include <cuda_bf16.h>
#include <cuda_fp16.h>
#include <cstdint>

// ---------------------------------------------------------------------------
// Problem constants
// ---------------------------------------------------------------------------
#define BATCH   4
#define NSEQ    2048
#define DIM     1024
#define HEADS   16
#define HDIM    64
#define M_ROWS  8192
#define N_COLS  3072
#define K_DIM   1024
#define SCALE   32.0f

// GEMM tiling (HMMA mma.sync path, single fp16 product)
#define QBM 128
#define QBN 128
#define KCH 64                      // K elems per chunk (64 fp16 = 128B rows)
#define NCHUNK (K_DIM / KCH)        // 16
#define STAGE_BYTES 32768           // A(16KB) + B(16KB)
#define NSTAGE 3
#define SMEM_DYN (NSTAGE * STAGE_BYTES)   // 98304 -> 2 CTAs/SM

// ---------------------------------------------------------------------------
// Scratch (device globals — allocation-free per harness rules)
// ---------------------------------------------------------------------------
__device__ __align__(16) __half g_Ah[(size_t)M_ROWS * K_DIM];      // fp16(x)
__device__ __align__(16) __half g_Bh[(size_t)N_COLS * K_DIM];      // W^T permuted fp16
__device__ float g_biasP[N_COLS];                                  // permuted bias
// Y layout (permuted): [row][t*1024 + h*64 + d]  (t: 0=q,1=k,2=v)
__device__ float g_Y[(size_t)M_ROWS * N_COLS];
__device__ float g_KVp[64 * 8 * HDIM * HDIM];
__device__ float g_KV[64 * HDIM * HDIM];

// ---------------------------------------------------------------------------
// Inline PTX (valid on base sm_103 target)
// ---------------------------------------------------------------------------
__device__ __forceinline__ uint32_t smem_u32(const void* p) {
    uint32_t a;
    asm("{ .reg .u64 t; cvta.to.shared.u64 t, %1; cvt.u32.u64 %0, t; }" : "=r"(a) : "l"(p));
    return a;
}
__device__ __forceinline__ void cp16(uint32_t dst, const void* src) {
    asm volatile("cp.async.cg.shared.global [%0], [%1], 16;" :: "r"(dst), "l"(src));
}
__device__ __forceinline__ void ldsm4(uint32_t* r, uint32_t addr) {
    asm volatile("ldmatrix.sync.aligned.m8n8.x4.shared.b16 {%0,%1,%2,%3}, [%4];"
        : "=r"(r[0]), "=r"(r[1]), "=r"(r[2]), "=r"(r[3]) : "r"(addr));
}
__device__ __forceinline__ void hmma(float* d, const uint32_t* a, const uint32_t* b) {
    asm volatile("mma.sync.aligned.m16n8k16.row.col.f32.f16.f16.f32 "
        "{%0,%1,%2,%3}, {%4,%5,%6,%7}, {%8,%9}, {%0,%1,%2,%3};"
        : "+f"(d[0]), "+f"(d[1]), "+f"(d[2]), "+f"(d[3])
        : "r"(a[0]), "r"(a[1]), "r"(a[2]), "r"(a[3]), "r"(b[0]), "r"(b[1]));
}

// ---------------------------------------------------------------------------
// conv_x: fp32 x -> fp16
// ---------------------------------------------------------------------------
__global__ __launch_bounds__(256)
void conv_x(const float4* __restrict__ x)
{
    size_t i = (size_t)blockIdx.x * 256 + threadIdx.x;
    float4 v = x[i];
    __half h[4];
    h[0] = __float2half(v.x); h[1] = __float2half(v.y);
    h[2] = __float2half(v.z); h[3] = __float2half(v.w);
    *(uint2*)(g_Ah + 4 * i) = *(uint2*)h;
}

// ---------------------------------------------------------------------------
// conv_w: W [k][c] -> permuted transposed fp16  g_Bh[c'][k]
// c = h*192 + d*3 + t  ->  c' = t*1024 + h*64 + d
// ---------------------------------------------------------------------------
__global__ __launch_bounds__(256)
void conv_w(const float* __restrict__ W)
{
    __shared__ float tile[32][193];
    const int h  = blockIdx.x;
    const int k0 = blockIdx.y * 32;
    const int tid = threadIdx.x;

    for (int e = tid; e < 32 * 192; e += 256) {
        int r = e / 192, cc = e % 192;
        tile[r][cc] = W[(size_t)(k0 + r) * N_COLS + h * 192 + cc];
    }
    __syncthreads();

    for (int e = tid; e < 3 * 64 * 32; e += 256) {
        int t = e >> 11;
        int rem = e & 2047;
        int d = rem >> 5, kk = rem & 31;
        float v = tile[kk][d * 3 + t];
        g_Bh[(size_t)(t * 1024 + h * 64 + d) * K_DIM + k0 + kk] = __float2half(v);
    }
}

__global__ __launch_bounds__(256)
void bias_perm(const float* __restrict__ bias)
{
    int cp = blockIdx.x * 256 + threadIdx.x;     // c'
    int t = cp >> 10, hd = cp & 1023, h = hd >> 6, d = hd & 63;
    g_biasP[cp] = bias[h * 192 + d * 3 + t];
}

// ---------------------------------------------------------------------------
// Kernel A: Y = X @ W' + bias' via mma.sync fp16, single product
// grid (24, 64), 256 threads (8 warps, 4x2), 2 CTAs/SM
// ---------------------------------------------------------------------------
__device__ __forceinline__ void load_chunk(uint32_t stage_sb, int rowBase, int colBase,
                                           int k0, int tid)
{
    // A: 1024 x 16B; B: 1024 x 16B; 8 cp16 per thread, coalesced
#pragma unroll
    for (int i = 0; i < 4; i++) {
        int o = tid + i * 256;
        int r = o >> 3, ch = o & 7;
        const __half* src = g_Ah + (size_t)(rowBase + r) * K_DIM + k0 + ch * 8;
        uint32_t dst = stage_sb + r * 128 + ((ch ^ (r & 7)) << 4);
        cp16(dst, src);
    }
#pragma unroll
    for (int i = 0; i < 4; i++) {
        int o = tid + i * 256;
        int r = o >> 3, ch = o & 7;
        const __half* src = g_Bh + (size_t)(colBase + r) * K_DIM + k0 + ch * 8;
        uint32_t dst = stage_sb + 16384 + r * 128 + ((ch ^ (r & 7)) << 4);
        cp16(dst, src);
    }
}

__global__ __launch_bounds__(256, 2)
void qkv_mma()
{
    extern __shared__ char smem[];
    const uint32_t sb = smem_u32(smem);
    const int tid = threadIdx.x;
    const int wid = tid >> 5, lid = tid & 31;
    const int warp_m = wid >> 1, warp_n = wid & 1;
    const int rowBase = blockIdx.y * QBM;
    const int colBase = blockIdx.x * QBN;

    float acc[2][8][4];
#pragma unroll
    for (int mt = 0; mt < 2; mt++)
#pragma unroll
        for (int nt = 0; nt < 8; nt++)
#pragma unroll
            for (int j = 0; j < 4; j++) acc[mt][nt][j] = 0.0f;

    // Prologue: fill all 3 stages
#pragma unroll
    for (int c = 0; c < NSTAGE; c++) {
        load_chunk(sb + c * STAGE_BYTES, rowBase, colBase, c * KCH, tid);
        asm volatile("cp.async.commit_group;" ::: "memory");
    }

    // ldmatrix invariants
    const uint32_t aRowOff = (uint32_t)(warp_m * 32 + (lid & 15)) * 128;
    // B x4: lanes 0-7 -> (ntPair*16 + 0..7, kchunk0), 8-15 -> same rows kchunk1,
    //       16-23 -> rows +8 kchunk0, 24-31 -> rows +8 kchunk1
    const uint32_t bRowOff = (uint32_t)(warp_n * 64 + (lid & 7) + ((lid >> 4) & 1) * 8) * 128;
    const int xorC   = lid & 7;
    const int chSelA = lid >> 4;          // 0/1
    const int chSelB = (lid >> 3) & 1;    // 0/1

    for (int c = 0; c < NCHUNK; c++) {
        asm volatile("cp.async.wait_group 2;" ::: "memory");
        __syncthreads();
        const uint32_t st = sb + (uint32_t)(c % NSTAGE) * STAGE_BYTES;

#pragma unroll
        for (int ks = 0; ks < 4; ks++) {
            const uint32_t chA = (uint32_t)((ks * 2 + chSelA) ^ xorC) << 4;
            const uint32_t chB = (uint32_t)((ks * 2 + chSelB) ^ xorC) << 4;
            uint32_t ah[2][4];
#pragma unroll
            for (int mt = 0; mt < 2; mt++)
                ldsm4(ah[mt], st + aRowOff + mt * (16 * 128) + chA);
            uint32_t bh[4][4];                 // [ntPair][4] -> nt=2p (r0,r1), nt=2p+1 (r2,r3)
#pragma unroll
            for (int p = 0; p < 4; p++)
                ldsm4(bh[p], st + 16384 + bRowOff + p * (16 * 128) + chB);
#pragma unroll
            for (int mt = 0; mt < 2; mt++)
#pragma unroll
                for (int p = 0; p < 4; p++) {
                    hmma(acc[mt][2 * p + 0], ah[mt], &bh[p][0]);
                    hmma(acc[mt][2 * p + 1], ah[mt], &bh[p][2]);
                }
        }
        __syncthreads();
        if (c + NSTAGE < NCHUNK)
            load_chunk(st, rowBase, colBase, (c + NSTAGE) * KCH, tid);
        asm volatile("cp.async.commit_group;" ::: "memory");
    }

    // Epilogue: + permuted bias -> g_Y
    const int er = rowBase + warp_m * 32 + (lid >> 2);
    const int ec = colBase + warp_n * 64 + (lid & 3) * 2;
    float2 bb[8];
#pragma unroll
    for (int nt = 0; nt < 8; nt++) bb[nt] = *(const float2*)&g_biasP[ec + nt * 8];
#pragma unroll
    for (int mt = 0; mt < 2; mt++) {
        const int r0 = er + mt * 16;
#pragma unroll
        for (int nt = 0; nt < 8; nt++) {
            float2 v0, v1;
            v0.x = acc[mt][nt][0] + bb[nt].x; v0.y = acc[mt][nt][1] + bb[nt].y;
            v1.x = acc[mt][nt][2] + bb[nt].x; v1.y = acc[mt][nt][3] + bb[nt].y;
            *(float2*)&g_Y[(size_t)r0 * N_COLS + ec + nt * 8] = v0;
            *(float2*)&g_Y[(size_t)(r0 + 8) * N_COLS + ec + nt * 8] = v1;
        }
    }
}

// ---------------------------------------------------------------------------
// Kernel B: per (b,h) partial KV[d1][d2] = sum_n k[n][d1] * v[n][d2]
// ---------------------------------------------------------------------------
__global__ __launch_bounds__(256)
void kv_partial()
{
    __shared__ float ks[32][HDIM];
    __shared__ float vs[32][HDIM];

    const int pair  = blockIdx.x;
    const int split = blockIdx.y;
    const int b = pair >> 4, h = pair & 15;
    const int tid = threadIdx.x;
    const int r4 = tid >> 4;
    const int c4 = tid & 15;

    float acc[4][4];
#pragma unroll
    for (int i = 0; i < 4; i++)
#pragma unroll
        for (int j = 0; j < 4; j++) acc[i][j] = 0.0f;

    const size_t rowBase = (size_t)b * NSEQ + (size_t)split * 256;
    const int kCol = 1024 + h * HDIM;
    const int vCol = 2048 + h * HDIM;

    for (int s = 0; s < 8; s++) {
        const int n0 = s * 32;
        for (int e = tid; e < 32 * HDIM; e += 256) {
            int nn = e >> 6, d = e & 63;
            size_t base = (rowBase + n0 + nn) * N_COLS;
            ks[nn][d] = g_Y[base + kCol + d];
            vs[nn][d] = g_Y[base + vCol + d];
        }
        __syncthreads();
#pragma unroll 4
        for (int nn = 0; nn < 32; nn++) {
            float ra[4], rb[4];
            *(float4*)ra = *(const float4*)&ks[nn][r4 * 4];
            *(float4*)rb = *(const float4*)&vs[nn][c4 * 4];
#pragma unroll
            for (int i = 0; i < 4; i++)
#pragma unroll
                for (int j = 0; j < 4; j++)
                    acc[i][j] += ra[i] * rb[j];
        }
        __syncthreads();
    }

    float* dst = g_KVp + ((size_t)pair * 8 + split) * (HDIM * HDIM);
#pragma unroll
    for (int i = 0; i < 4; i++)
#pragma unroll
        for (int j = 0; j < 4; j++)
            dst[(r4 * 4 + i) * HDIM + c4 * 4 + j] = acc[i][j];
}

__global__ __launch_bounds__(256)
void kv_reduce()
{
    int idx = blockIdx.x * 256 + threadIdx.x;
    int pair = idx >> 12, off = idx & 4095;
    const float* src = g_KVp + ((size_t)pair * 8) * 4096 + off;
    float s = 0.0f;
#pragma unroll
    for (int k = 0; k < 8; k++) s += src[(size_t)k * 4096];
    g_KV[idx] = s * SCALE;
}

// ---------------------------------------------------------------------------
// Kernel C: out = q @ KV   (j-outer, 32 independent accumulators/thread)
// ---------------------------------------------------------------------------
#define SMEM_OUT (128 * 65 * 4 + 64 * 64 * 4)   // 49664

__global__ __launch_bounds__(256)
void out_gemm(float* __restrict__ out)
{
    extern __shared__ char smc[];
    float (*qs)[65] = (float(*)[65])smc;
    float (*kvs)[64] = (float(*)[64])(smc + 128 * 65 * 4);

    const int pair = blockIdx.x;
    const int nc   = blockIdx.y;
    const int b = pair >> 4, h = pair & 15;
    const int tid = threadIdx.x;

    const size_t rowBase = (size_t)b * NSEQ + (size_t)nc * 128;
    const int qCol = h * HDIM;

    for (int e = tid; e < 128 * HDIM; e += 256) {
        int r = e >> 6, d = e & 63;
        qs[r][d] = g_Y[(rowBase + r) * N_COLS + qCol + d];
    }
    const float* kvsrc = g_KV + (size_t)pair * (HDIM * HDIM);
    for (int e = tid; e < HDIM * HDIM; e += 256)
        ((float*)kvs)[e] = kvsrc[e];
    __syncthreads();

    const int dg = (tid & 7) * 8;
    const int rg = (tid >> 3) * 4;

    float acc[4][8];
#pragma unroll
    for (int i = 0; i < 4; i++)
#pragma unroll
        for (int j = 0; j < 8; j++) acc[i][j] = 0.0f;

#pragma unroll 4
    for (int j = 0; j < HDIM; j++) {
        float4 kv0 = *(const float4*)&kvs[j][dg];
        float4 kv1 = *(const float4*)&kvs[j][dg + 4];
        float q0 = qs[rg + 0][j], q1 = qs[rg + 1][j];
        float q2 = qs[rg + 2][j], q3 = qs[rg + 3][j];
        acc[0][0] += q0 * kv0.x; acc[0][1] += q0 * kv0.y; acc[0][2] += q0 * kv0.z; acc[0][3] += q0 * kv0.w;
        acc[0][4] += q0 * kv1.x; acc[0][5] += q0 * kv1.y; acc[0][6] += q0 * kv1.z; acc[0][7] += q0 * kv1.w;
        acc[1][0] += q1 * kv0.x; acc[1][1] += q1 * kv0.y; acc[1][2] += q1 * kv0.z; acc[1][3] += q1 * kv0.w;
        acc[1][4] += q1 * kv1.x; acc[1][5] += q1 * kv1.y; acc[1][6] += q1 * kv1.z; acc[1][7] += q1 * kv1.w;
        acc[2][0] += q2 * kv0.x; acc[2][1] += q2 * kv0.y; acc[2][2] += q2 * kv0.z; acc[2][3] += q2 * kv0.w;
        acc[2][4] += q2 * kv1.x; acc[2][5] += q2 * kv1.y; acc[2][6] += q2 * kv1.z; acc[2][7] += q2 * kv1.w;
        acc[3][0] += q3 * kv0.x; acc[3][1] += q3 * kv0.y; acc[3][2] += q3 * kv0.z; acc[3][3] += q3 * kv0.w;
        acc[3][4] += q3 * kv1.x; acc[3][5] += q3 * kv1.y; acc[3][6] += q3 * kv1.z; acc[3][7] += q3 * kv1.w;
    }

    float* obase = out + ((size_t)pair * NSEQ + (size_t)nc * 128) * HDIM;
#pragma unroll
    for (int rr = 0; rr < 4; rr++) {
        *(float4*)&obase[(size_t)(rg + rr) * HDIM + dg]     = *(float4*)&acc[rr][0];
        *(float4*)&obase[(size_t)(rg + rr) * HDIM + dg + 4] = *(float4*)&acc[rr][4];
    }
}

// ---------------------------------------------------------------------------
// Host launch
// ---------------------------------------------------------------------------
extern "C" void kernel_launch(void* const* d_in, const int* in_sizes, int n_in,
                              void* d_out, int out_size)
{
    (void)in_sizes; (void)n_in; (void)out_size;
    const float* x    = (const float*)d_in[0];
    const float* W    = (const float*)d_in[1];
    const float* bias = (const float*)d_in[2];
    float* out = (float*)d_out;

    static int attr_set = 0;
    if (!attr_set) {
        cudaFuncSetAttribute(qkv_mma, cudaFuncAttributeMaxDynamicSharedMemorySize, SMEM_DYN);
        cudaFuncSetAttribute(out_gemm, cudaFuncAttributeMaxDynamicSharedMemorySize, SMEM_OUT);
        attr_set = 1;
    }

    conv_x<<<(M_ROWS * K_DIM / 4) / 256, 256>>>((const float4*)x);
    conv_w<<<dim3(16, 32), 256>>>(W);
    bias_perm<<<N_COLS / 256, 256>>>(bias);

    qkv_mma<<<dim3(N_COLS / QBN, M_ROWS / QBM), 256, SMEM_DYN>>>();

    kv_partial<<<dim3(64, 8), 256>>>();
    kv_reduce<<<(64 * HDIM * HDIM) / 256, 256>>>();
    out_gemm<<<dim3(64, 16), 256, SMEM_OUT>>>(out);
}

// round 6
// speedup vs baseline: 7.0840x; 1.4672x over previous
#include <cuda_runtime.h>
#include <cuda_fp16.h>
#include <cstdint>

// ---------------------------------------------------------------------------
// Problem constants
// ---------------------------------------------------------------------------
#define BATCH   4
#define NSEQ    2048
#define DIM     1024
#define HEADS   16
#define HDIM    64
#define M_ROWS  8192
#define N_COLS  3072
#define K_DIM   1024
#define SCALE   32.0f

// qkv GEMM tiling (unchanged, at legacy-HMMA roofline)
#define QBM 128
#define QBN 128
#define KCH 64
#define NCHUNK (K_DIM / KCH)
#define STAGE_BYTES 32768
#define NSTAGE 3
#define SMEM_DYN (NSTAGE * STAGE_BYTES)

#define KV_SMEM  65536     // v tile 32KB + k tile 32KB
#define OUT_SMEM 49152     // q 32KB + KVT hi 8KB + KVT lo 8KB

// ---------------------------------------------------------------------------
// Scratch (device globals — allocation-free per harness rules)
// ---------------------------------------------------------------------------
__device__ __align__(16) __half g_Ah[(size_t)M_ROWS * K_DIM];      // fp16(x)
__device__ __align__(16) __half g_Bh[(size_t)N_COLS * K_DIM];      // W^T permuted fp16
__device__ float g_biasP[N_COLS];
// Y fp16, permuted: [row][t*1024 + h*64 + d]
__device__ __align__(16) __half g_Y16[(size_t)M_ROWS * N_COLS];
__device__ float g_KVp[64 * 8 * HDIM * HDIM];                      // KV^T partials [d2][d1]
__device__ __align__(16) __half g_KVThi[64 * HDIM * HDIM];         // scale*KV^T hi
__device__ __align__(16) __half g_KVTlo[64 * HDIM * HDIM];         // scale*KV^T lo

// ---------------------------------------------------------------------------
// Inline PTX (valid on base sm_103 target)
// ---------------------------------------------------------------------------
__device__ __forceinline__ uint32_t smem_u32(const void* p) {
    uint32_t a;
    asm("{ .reg .u64 t; cvta.to.shared.u64 t, %1; cvt.u32.u64 %0, t; }" : "=r"(a) : "l"(p));
    return a;
}
__device__ __forceinline__ void cp16(uint32_t dst, const void* src) {
    asm volatile("cp.async.cg.shared.global [%0], [%1], 16;" :: "r"(dst), "l"(src));
}
__device__ __forceinline__ void ldsm4(uint32_t* r, uint32_t addr) {
    asm volatile("ldmatrix.sync.aligned.m8n8.x4.shared.b16 {%0,%1,%2,%3}, [%4];"
        : "=r"(r[0]), "=r"(r[1]), "=r"(r[2]), "=r"(r[3]) : "r"(addr));
}
__device__ __forceinline__ void ldsm4t(uint32_t* r, uint32_t addr) {
    asm volatile("ldmatrix.sync.aligned.m8n8.x4.trans.shared.b16 {%0,%1,%2,%3}, [%4];"
        : "=r"(r[0]), "=r"(r[1]), "=r"(r[2]), "=r"(r[3]) : "r"(addr));
}
__device__ __forceinline__ void hmma(float* d, const uint32_t* a, const uint32_t* b) {
    asm volatile("mma.sync.aligned.m16n8k16.row.col.f32.f16.f16.f32 "
        "{%0,%1,%2,%3}, {%4,%5,%6,%7}, {%8,%9}, {%0,%1,%2,%3};"
        : "+f"(d[0]), "+f"(d[1]), "+f"(d[2]), "+f"(d[3])
        : "r"(a[0]), "r"(a[1]), "r"(a[2]), "r"(a[3]), "r"(b[0]), "r"(b[1]));
}

// ---------------------------------------------------------------------------
// conv_x: fp32 x -> fp16
// ---------------------------------------------------------------------------
__global__ __launch_bounds__(256)
void conv_x(const float4* __restrict__ x)
{
    size_t i = (size_t)blockIdx.x * 256 + threadIdx.x;
    float4 v = x[i];
    __half h[4];
    h[0] = __float2half(v.x); h[1] = __float2half(v.y);
    h[2] = __float2half(v.z); h[3] = __float2half(v.w);
    *(uint2*)(g_Ah + 4 * i) = *(uint2*)h;
}

// ---------------------------------------------------------------------------
// conv_w: W [k][c] -> permuted transposed fp16  g_Bh[c'][k]
// c = h*192 + d*3 + t  ->  c' = t*1024 + h*64 + d
// ---------------------------------------------------------------------------
__global__ __launch_bounds__(256)
void conv_w(const float* __restrict__ W)
{
    __shared__ float tile[32][193];
    const int h  = blockIdx.x;
    const int k0 = blockIdx.y * 32;
    const int tid = threadIdx.x;

    for (int e = tid; e < 32 * 192; e += 256) {
        int r = e / 192, cc = e % 192;
        tile[r][cc] = W[(size_t)(k0 + r) * N_COLS + h * 192 + cc];
    }
    __syncthreads();

    for (int e = tid; e < 3 * 64 * 32; e += 256) {
        int t = e >> 11;
        int rem = e & 2047;
        int d = rem >> 5, kk = rem & 31;
        float v = tile[kk][d * 3 + t];
        g_Bh[(size_t)(t * 1024 + h * 64 + d) * K_DIM + k0 + kk] = __float2half(v);
    }
}

__global__ __launch_bounds__(256)
void bias_perm(const float* __restrict__ bias)
{
    int cp = blockIdx.x * 256 + threadIdx.x;
    int t = cp >> 10, hd = cp & 1023, h = hd >> 6, d = hd & 63;
    g_biasP[cp] = bias[h * 192 + d * 3 + t];
}

// ---------------------------------------------------------------------------
// Kernel A: Y16 = fp16(X @ W' + bias') via mma.sync fp16
// grid (24, 64), 256 threads (8 warps, 4x2), 2 CTAs/SM
// ---------------------------------------------------------------------------
__device__ __forceinline__ void load_chunk(uint32_t stage_sb, int rowBase, int colBase,
                                           int k0, int tid)
{
#pragma unroll
    for (int i = 0; i < 4; i++) {
        int o = tid + i * 256;
        int r = o >> 3, ch = o & 7;
        const __half* src = g_Ah + (size_t)(rowBase + r) * K_DIM + k0 + ch * 8;
        uint32_t dst = stage_sb + r * 128 + ((ch ^ (r & 7)) << 4);
        cp16(dst, src);
    }
#pragma unroll
    for (int i = 0; i < 4; i++) {
        int o = tid + i * 256;
        int r = o >> 3, ch = o & 7;
        const __half* src = g_Bh + (size_t)(colBase + r) * K_DIM + k0 + ch * 8;
        uint32_t dst = stage_sb + 16384 + r * 128 + ((ch ^ (r & 7)) << 4);
        cp16(dst, src);
    }
}

__global__ __launch_bounds__(256, 2)
void qkv_mma()
{
    extern __shared__ char smem[];
    const uint32_t sb = smem_u32(smem);
    const int tid = threadIdx.x;
    const int wid = tid >> 5, lid = tid & 31;
    const int warp_m = wid >> 1, warp_n = wid & 1;
    const int rowBase = blockIdx.y * QBM;
    const int colBase = blockIdx.x * QBN;

    float acc[2][8][4];
#pragma unroll
    for (int mt = 0; mt < 2; mt++)
#pragma unroll
        for (int nt = 0; nt < 8; nt++)
#pragma unroll
            for (int j = 0; j < 4; j++) acc[mt][nt][j] = 0.0f;

#pragma unroll
    for (int c = 0; c < NSTAGE; c++) {
        load_chunk(sb + c * STAGE_BYTES, rowBase, colBase, c * KCH, tid);
        asm volatile("cp.async.commit_group;" ::: "memory");
    }

    const uint32_t aRowOff = (uint32_t)(warp_m * 32 + (lid & 15)) * 128;
    const uint32_t bRowOff = (uint32_t)(warp_n * 64 + (lid & 7) + ((lid >> 4) & 1) * 8) * 128;
    const int xorC   = lid & 7;
    const int chSelA = lid >> 4;
    const int chSelB = (lid >> 3) & 1;

    for (int c = 0; c < NCHUNK; c++) {
        asm volatile("cp.async.wait_group 2;" ::: "memory");
        __syncthreads();
        const uint32_t st = sb + (uint32_t)(c % NSTAGE) * STAGE_BYTES;

#pragma unroll
        for (int ks = 0; ks < 4; ks++) {
            const uint32_t chA = (uint32_t)((ks * 2 + chSelA) ^ xorC) << 4;
            const uint32_t chB = (uint32_t)((ks * 2 + chSelB) ^ xorC) << 4;
            uint32_t ah[2][4];
#pragma unroll
            for (int mt = 0; mt < 2; mt++)
                ldsm4(ah[mt], st + aRowOff + mt * (16 * 128) + chA);
            uint32_t bh[4][4];
#pragma unroll
            for (int p = 0; p < 4; p++)
                ldsm4(bh[p], st + 16384 + bRowOff + p * (16 * 128) + chB);
#pragma unroll
            for (int mt = 0; mt < 2; mt++)
#pragma unroll
                for (int p = 0; p < 4; p++) {
                    hmma(acc[mt][2 * p + 0], ah[mt], &bh[p][0]);
                    hmma(acc[mt][2 * p + 1], ah[mt], &bh[p][2]);
                }
        }
        __syncthreads();
        if (c + NSTAGE < NCHUNK)
            load_chunk(st, rowBase, colBase, (c + NSTAGE) * KCH, tid);
        asm volatile("cp.async.commit_group;" ::: "memory");
    }

    // Epilogue: + bias -> fp16 Y
    const int er = rowBase + warp_m * 32 + (lid >> 2);
    const int ec = colBase + warp_n * 64 + (lid & 3) * 2;
    float2 bb[8];
#pragma unroll
    for (int nt = 0; nt < 8; nt++) bb[nt] = *(const float2*)&g_biasP[ec + nt * 8];
#pragma unroll
    for (int mt = 0; mt < 2; mt++) {
        const int r0 = er + mt * 16;
#pragma unroll
        for (int nt = 0; nt < 8; nt++) {
            __half2 v0 = __floats2half2_rn(acc[mt][nt][0] + bb[nt].x,
                                           acc[mt][nt][1] + bb[nt].y);
            __half2 v1 = __floats2half2_rn(acc[mt][nt][2] + bb[nt].x,
                                           acc[mt][nt][3] + bb[nt].y);
            *(__half2*)&g_Y16[(size_t)r0 * N_COLS + ec + nt * 8] = v0;
            *(__half2*)&g_Y16[(size_t)(r0 + 8) * N_COLS + ec + nt * 8] = v1;
        }
    }
}

// ---------------------------------------------------------------------------
// Kernel B: KV^T partials via HMMA.  KV^T[d2][d1] = sum_n v[n][d2]^T k[n][d1]
// A = v^T (trans ldmatrix), B = k (trans ldmatrix). grid (64, 8), 128 threads.
// ---------------------------------------------------------------------------
__global__ __launch_bounds__(128)
void kv_partial()
{
    extern __shared__ char smc[];
    const uint32_t sv = smem_u32(smc);            // v tile [256][64] fp16, swizzled
    const uint32_t sk = sv + 32768;               // k tile
    const int pair  = blockIdx.x;
    const int split = blockIdx.y;
    const int b = pair >> 4, h = pair & 15;
    const int tid = threadIdx.x;
    const int wid = tid >> 5, lid = tid & 31;

    const size_t rowBase = (size_t)b * NSEQ + (size_t)split * 256;
    const int kCol = 1024 + h * HDIM;
    const int vCol = 2048 + h * HDIM;

    // Fill both tiles: 2048 cp16 each, 16 per thread per tile
#pragma unroll
    for (int i = 0; i < 16; i++) {
        int o = tid + i * 128;
        int r = o >> 3, ch = o & 7;
        uint32_t sw = r * 128 + ((ch ^ (r & 7)) << 4);
        cp16(sv + sw, g_Y16 + (rowBase + r) * N_COLS + vCol + ch * 8);
        cp16(sk + sw, g_Y16 + (rowBase + r) * N_COLS + kCol + ch * 8);
    }
    asm volatile("cp.async.commit_group;" ::: "memory");
    asm volatile("cp.async.wait_group 0;" ::: "memory");
    __syncthreads();

    float acc[4][2][4];
#pragma unroll
    for (int mt = 0; mt < 4; mt++)
#pragma unroll
        for (int bn = 0; bn < 2; bn++)
#pragma unroll
            for (int j = 0; j < 4; j++) acc[mt][bn][j] = 0.0f;

    // trans-ldmatrix lane addressing
    const int krA = (lid & 7) | ((lid & 16) >> 1);   // A source row (k), bit3 from lane bit4
    const int mSel = (lid >> 3) & 1;                 // A source col chunk low bit
    const int krB = lid & 15;                        // B source row (k)
    const int nSel = lid >> 4;                       // B source col chunk low bit
    const int xA = krA & 7;                          // == lid&7
    const int xB = krB & 7;

    for (int ks = 0; ks < 16; ks++) {
        const int rowA = ks * 16 + krA;
        const int rowB = ks * 16 + krB;
        uint32_t a[4][4];
#pragma unroll
        for (int mt = 0; mt < 4; mt++) {
            uint32_t ch = (uint32_t)((mt * 2 + mSel) ^ xA) << 4;
            ldsm4t(a[mt], sv + rowA * 128 + ch);
        }
        uint32_t bf[4];
        {
            uint32_t ch = (uint32_t)((wid * 2 + nSel) ^ xB) << 4;
            ldsm4t(bf, sk + rowB * 128 + ch);
        }
#pragma unroll
        for (int mt = 0; mt < 4; mt++) {
            hmma(acc[mt][0], a[mt], &bf[0]);
            hmma(acc[mt][1], a[mt], &bf[2]);
        }
    }

    // Store partials: [d2][d1] layout
    float* dst = g_KVp + ((size_t)pair * 8 + split) * (HDIM * HDIM);
    const int d1c = wid * 16 + (lid & 3) * 2;
#pragma unroll
    for (int mt = 0; mt < 4; mt++) {
        const int d2r = mt * 16 + (lid >> 2);
#pragma unroll
        for (int bn = 0; bn < 2; bn++) {
            *(float2*)&dst[(size_t)d2r * HDIM + d1c + bn * 8] =
                *(float2*)&acc[mt][bn][0];
            *(float2*)&dst[(size_t)(d2r + 8) * HDIM + d1c + bn * 8] =
                *(float2*)&acc[mt][bn][2];
        }
    }
}

// ---------------------------------------------------------------------------
// kv_reduce: sum 8 splits, scale, split to fp16 hi+lo (KV^T layout kept)
// ---------------------------------------------------------------------------
__global__ __launch_bounds__(256)
void kv_reduce()
{
    int idx = blockIdx.x * 256 + threadIdx.x;
    int pair = idx >> 12, off = idx & 4095;
    const float* src = g_KVp + ((size_t)pair * 8) * 4096 + off;
    float s = 0.0f;
#pragma unroll
    for (int k = 0; k < 8; k++) s += src[(size_t)k * 4096];
    s *= SCALE;
    __half hi = __float2half(s);
    __half lo = __float2half(s - __half2float(hi));
    g_KVThi[idx] = hi;
    g_KVTlo[idx] = lo;
}

// ---------------------------------------------------------------------------
// Kernel C: out = q @ KV via HMMA.  A = q fp16, B = KVT hi + KVT lo.
// grid (64 pairs, 8 chunks of 256 rows), 256 threads (8 warps, m-split).
// ---------------------------------------------------------------------------
__global__ __launch_bounds__(256)
void out_gemm(float* __restrict__ out)
{
    extern __shared__ char smc[];
    const uint32_t sq  = smem_u32(smc);          // q tile [256][64] fp16, swizzled
    const uint32_t sbh = sq + 32768;             // KVT hi [64][64]
    const uint32_t sbl = sbh + 8192;             // KVT lo

    const int pair = blockIdx.x;
    const int nc   = blockIdx.y;
    const int b = pair >> 4, h = pair & 15;
    const int tid = threadIdx.x;
    const int wid = tid >> 5, lid = tid & 31;

    const size_t rowBaseQ = (size_t)b * NSEQ + (size_t)nc * 256;
    const int qCol = h * HDIM;

    // Fill q tile: 2048 cp16, 8 per thread
#pragma unroll
    for (int i = 0; i < 8; i++) {
        int o = tid + i * 256;
        int r = o >> 3, ch = o & 7;
        uint32_t sw = r * 128 + ((ch ^ (r & 7)) << 4);
        cp16(sq + sw, g_Y16 + (rowBaseQ + r) * N_COLS + qCol + ch * 8);
    }
    // Fill KVT hi/lo: 512 cp16 each, 2 per thread each
    const __half* kvh = g_KVThi + (size_t)pair * 4096;
    const __half* kvl = g_KVTlo + (size_t)pair * 4096;
#pragma unroll
    for (int i = 0; i < 2; i++) {
        int o = tid + i * 256;
        int r = o >> 3, ch = o & 7;
        uint32_t sw = r * 128 + ((ch ^ (r & 7)) << 4);
        cp16(sbh + sw, kvh + r * 64 + ch * 8);
        cp16(sbl + sw, kvl + r * 64 + ch * 8);
    }
    asm volatile("cp.async.commit_group;" ::: "memory");
    asm volatile("cp.async.wait_group 0;" ::: "memory");
    __syncthreads();

    float acc[2][8][4];
#pragma unroll
    for (int mt = 0; mt < 2; mt++)
#pragma unroll
        for (int nt = 0; nt < 8; nt++)
#pragma unroll
            for (int j = 0; j < 4; j++) acc[mt][nt][j] = 0.0f;

    const uint32_t aRowOff = (uint32_t)(wid * 32 + (lid & 15)) * 128;
    const uint32_t bRowOff = (uint32_t)((lid & 7) + ((lid >> 4) & 1) * 8) * 128;
    const int xorC   = lid & 7;
    const int chSelA = lid >> 4;
    const int chSelB = (lid >> 3) & 1;

#pragma unroll
    for (int ks = 0; ks < 4; ks++) {
        const uint32_t chA = (uint32_t)((ks * 2 + chSelA) ^ xorC) << 4;
        const uint32_t chB = (uint32_t)((ks * 2 + chSelB) ^ xorC) << 4;
        uint32_t a[2][4];
#pragma unroll
        for (int mt = 0; mt < 2; mt++)
            ldsm4(a[mt], sq + aRowOff + mt * (16 * 128) + chA);
        uint32_t bh[4][4], bl[4][4];
#pragma unroll
        for (int p = 0; p < 4; p++) {
            ldsm4(bh[p], sbh + bRowOff + p * (16 * 128) + chB);
            ldsm4(bl[p], sbl + bRowOff + p * (16 * 128) + chB);
        }
#pragma unroll
        for (int mt = 0; mt < 2; mt++)
#pragma unroll
            for (int p = 0; p < 4; p++) {
                hmma(acc[mt][2 * p + 0], a[mt], &bh[p][0]);
                hmma(acc[mt][2 * p + 1], a[mt], &bh[p][2]);
                hmma(acc[mt][2 * p + 0], a[mt], &bl[p][0]);
                hmma(acc[mt][2 * p + 1], a[mt], &bl[p][2]);
            }
    }

    // Store: out[pair][n][d2]
    float* obase = out + ((size_t)pair * NSEQ + (size_t)nc * 256) * HDIM;
    const int ec = (lid & 3) * 2;
#pragma unroll
    for (int mt = 0; mt < 2; mt++) {
        const int r0 = wid * 32 + mt * 16 + (lid >> 2);
#pragma unroll
        for (int nt = 0; nt < 8; nt++) {
            *(float2*)&obase[(size_t)r0 * HDIM + ec + nt * 8] =
                *(float2*)&acc[mt][nt][0];
            *(float2*)&obase[(size_t)(r0 + 8) * HDIM + ec + nt * 8] =
                *(float2*)&acc[mt][nt][2];
        }
    }
}

// ---------------------------------------------------------------------------
// Host launch
// ---------------------------------------------------------------------------
extern "C" void kernel_launch(void* const* d_in, const int* in_sizes, int n_in,
                              void* d_out, int out_size)
{
    (void)in_sizes; (void)n_in; (void)out_size;
    const float* x    = (const float*)d_in[0];
    const float* W    = (const float*)d_in[1];
    const float* bias = (const float*)d_in[2];
    float* out = (float*)d_out;

    static int attr_set = 0;
    if (!attr_set) {
        cudaFuncSetAttribute(qkv_mma, cudaFuncAttributeMaxDynamicSharedMemorySize, SMEM_DYN);
        cudaFuncSetAttribute(kv_partial, cudaFuncAttributeMaxDynamicSharedMemorySize, KV_SMEM);
        cudaFuncSetAttribute(out_gemm, cudaFuncAttributeMaxDynamicSharedMemorySize, OUT_SMEM);
        attr_set = 1;
    }

    conv_x<<<(M_ROWS * K_DIM / 4) / 256, 256>>>((const float4*)x);
    conv_w<<<dim3(16, 32), 256>>>(W);
    bias_perm<<<N_COLS / 256, 256>>>(bias);

    qkv_mma<<<dim3(N_COLS / QBN, M_ROWS / QBM), 256, SMEM_DYN>>>();

    kv_partial<<<dim3(64, 8), 128, KV_SMEM>>>();
    kv_reduce<<<(64 * HDIM * HDIM) / 256, 256>>>();
    out_gemm<<<dim3(64, 8), 256, OUT_SMEM>>>(out);
}